// round 4
// baseline (speedup 1.0000x reference)
#include <cuda_runtime.h>
#include <cuda_bf16.h>
#include <cstdint>
#include <math.h>

#define DIM    256
#define HEADS  8
#define HD     32
#define N1V    256
#define N2V    256
#define BTOT   256
#define NWIN   128
#define TBL    1575
#define MTOT   (BTOT * N1V)          // 65536 rows

// ---------------- scratch (device globals; no allocation) ----------------
__device__ float d_qh [MTOT * DIM];              // fp32 Q proj (scaled)
__device__ float d_kvh[MTOT * 2 * DIM];          // fp32 K|V proj
__device__ __nv_bfloat16 d_qhi [MTOT * DIM];
__device__ __nv_bfloat16 d_qlo [MTOT * DIM];
__device__ __nv_bfloat16 d_kvhi[MTOT * DIM];
__device__ __nv_bfloat16 d_kvlo[MTOT * DIM];
__device__ __nv_bfloat16 d_xhi [MTOT * DIM];
__device__ __nv_bfloat16 d_xlo [MTOT * DIM];
__device__ __nv_bfloat16 d_wqhi [DIM * DIM],     d_wqlo [DIM * DIM];
__device__ __nv_bfloat16 d_wkvhi[2 * DIM * DIM], d_wkvlo[2 * DIM * DIM];
__device__ __nv_bfloat16 d_wphi [DIM * DIM],     d_wplo [DIM * DIM];

// ---------------- helpers ----------------
__device__ __forceinline__ uint32_t smem_u32(const void* p) {
    uint32_t a;
    asm("{ .reg .u64 t; cvta.to.shared.u64 t, %1; cvt.u32.u64 %0, t; }"
        : "=r"(a) : "l"(p));
    return a;
}
#define LDSM_X4(r0, r1, r2, r3, addr) \
    asm volatile("ldmatrix.sync.aligned.m8n8.x4.shared.b16 {%0,%1,%2,%3}, [%4];" \
                 : "=r"(r0), "=r"(r1), "=r"(r2), "=r"(r3) : "r"(addr))
#define MMA16816(d, a, b0v, b1v) \
    asm volatile("mma.sync.aligned.m16n8k16.row.col.f32.bf16.bf16.f32 " \
                 "{%0,%1,%2,%3}, {%4,%5,%6,%7}, {%8,%9}, {%0,%1,%2,%3};" \
                 : "+f"((d)[0]), "+f"((d)[1]), "+f"((d)[2]), "+f"((d)[3]) \
                 : "r"((a)[0]), "r"((a)[1]), "r"((a)[2]), "r"((a)[3]), \
                   "r"(b0v), "r"(b1v))

// ---------------- fp32 -> (bf16 hi, bf16 lo) split ----------------
__global__ void __launch_bounds__(256) split_kernel(
    const float* __restrict__ x, __nv_bfloat162* __restrict__ hi,
    __nv_bfloat162* __restrict__ lo, int n2)
{
    int i = blockIdx.x * 256 + threadIdx.x;
    if (i >= n2) return;
    float2 v = ((const float2*)x)[i];
    __nv_bfloat16 h0 = __float2bfloat16_rn(v.x);
    __nv_bfloat16 h1 = __float2bfloat16_rn(v.y);
    float r0 = v.x - __bfloat162float(h0);
    float r1 = v.y - __bfloat162float(h1);
    __nv_bfloat162 H; H.x = h0; H.y = h1;
    __nv_bfloat162 L; L.x = __float2bfloat16_rn(r0); L.y = __float2bfloat16_rn(r1);
    hi[i] = H; lo[i] = L;
}

// ---------------- warp-MMA split-bf16 GEMM ----------------
// C[M,N] = alpha * ( Ahi@Bhi^T + Alo@Bhi^T + Ahi@Blo^T + bias )
// A*: [M,256] bf16 row-major, B*: [N,256] bf16 row-major.
// Block tile 128x128, 256 threads (8 warps as 4x2), warp tile 32x64.
#define SSTR 72   // smem row stride in bf16 elems (144B: 16B-aligned, conflict-free)

__global__ void __launch_bounds__(256) mma_gemm(
    const __nv_bfloat16* __restrict__ Ahi, const __nv_bfloat16* __restrict__ Alo,
    const __nv_bfloat16* __restrict__ Bhi, const __nv_bfloat16* __restrict__ Blo,
    const float* __restrict__ bias, float* __restrict__ C, int N, float alpha)
{
    __shared__ __nv_bfloat16 As[128][SSTR];
    __shared__ __nv_bfloat16 Bs[128][SSTR];
    __shared__ float sbias[128];

    const int tid  = threadIdx.x;
    const int lane = tid & 31;
    const int wid  = tid >> 5;
    const int wr   = wid & 3;        // 0..3 -> m offset wr*32
    const int wc   = wid >> 2;       // 0..1 -> n offset wc*64
    const int m0   = blockIdx.y * 128;
    const int n0   = blockIdx.x * 128;

    if (tid < 128) sbias[tid] = bias[n0 + tid];

    float acc[2][8][4] = {};
    const uint32_t aB = smem_u32(As);
    const uint32_t bB = smem_u32(Bs);

    // precompute ldmatrix base addresses (kk adds 32B per k16 step)
    uint32_t aAddr[2], bAddr[4];
#pragma unroll
    for (int mt = 0; mt < 2; mt++)
        aAddr[mt] = aB + (uint32_t)(((wr * 32 + mt * 16 + (lane & 15)) * SSTR
                                     + (lane >> 4) * 8) * 2);
#pragma unroll
    for (int ng = 0; ng < 4; ng++)
        bAddr[ng] = bB + (uint32_t)(((wc * 64 + ng * 16 + (lane & 7)
                                      + ((lane >> 4) & 1) * 8) * SSTR
                                     + ((lane >> 3) & 1) * 8) * 2);

#pragma unroll 1
    for (int seg = 0; seg < 3; seg++) {
        const __nv_bfloat16* Ag = (seg == 1) ? Alo : Ahi;
        const __nv_bfloat16* Bg = (seg == 2) ? Blo : Bhi;
#pragma unroll 1
        for (int kc = 0; kc < 4; kc++) {
            const int k0 = kc * 64;
            __syncthreads();                     // previous iter's reads done
#pragma unroll
            for (int i = 0; i < 4; i++) {
                int li = tid + i * 256;          // 0..1023 16B units
                int r  = li >> 3;
                int u  = (li & 7) * 8;
                *(uint4*)&As[r][u] = *(const uint4*)(Ag + (size_t)(m0 + r) * 256 + k0 + u);
                *(uint4*)&Bs[r][u] = *(const uint4*)(Bg + (size_t)(n0 + r) * 256 + k0 + u);
            }
            __syncthreads();
#pragma unroll
            for (int kk = 0; kk < 4; kk++) {
                const uint32_t ko = (uint32_t)(kk * 16 * 2);
                uint32_t a[2][4], b[4][4];
#pragma unroll
                for (int mt = 0; mt < 2; mt++)
                    LDSM_X4(a[mt][0], a[mt][1], a[mt][2], a[mt][3], aAddr[mt] + ko);
#pragma unroll
                for (int ng = 0; ng < 4; ng++)
                    LDSM_X4(b[ng][0], b[ng][1], b[ng][2], b[ng][3], bAddr[ng] + ko);
#pragma unroll
                for (int mt = 0; mt < 2; mt++)
#pragma unroll
                    for (int nt = 0; nt < 8; nt++)
                        MMA16816(acc[mt][nt], a[mt],
                                 b[nt >> 1][(nt & 1) * 2],
                                 b[nt >> 1][(nt & 1) * 2 + 1]);
            }
        }
    }
    __syncthreads();

    // epilogue: d0,d1 -> row g, cols 2t..2t+1 ; d2,d3 -> row g+8
    const int g  = lane >> 2;
    const int tg = lane & 3;
#pragma unroll
    for (int mt = 0; mt < 2; mt++) {
        const int row = m0 + wr * 32 + mt * 16 + g;
#pragma unroll
        for (int nt = 0; nt < 8; nt++) {
            const int col = wc * 64 + nt * 8 + tg * 2;
            const float b0 = sbias[col], b1 = sbias[col + 1];
            float2 v0, v1;
            v0.x = alpha * (acc[mt][nt][0] + b0);
            v0.y = alpha * (acc[mt][nt][1] + b1);
            v1.x = alpha * (acc[mt][nt][2] + b0);
            v1.y = alpha * (acc[mt][nt][3] + b1);
            *(float2*)(C + (size_t)row * N + n0 + col)       = v0;
            *(float2*)(C + (size_t)(row + 8) * N + n0 + col) = v1;
        }
    }
}

// ---------------- attention kernel (fp32; emits bf16 hi/lo) ----------------
struct __align__(16) AttnSmem {
    union U {
        float K[256][32];
        struct { float Ms[64][65]; unsigned short Ri[64][66]; } mb;
    } u;
    float Qs[64][33];
    float btab[TBL];
    float red[64][4];
    float linv[64];
};

__global__ void __launch_bounds__(256) attn_kernel(
    const float* __restrict__ qh, const float* __restrict__ kvh,
    const float* __restrict__ mask, const float* __restrict__ btab_g,
    const int* __restrict__ rel,
    __nv_bfloat16* __restrict__ xhi, __nv_bfloat16* __restrict__ xlo)
{
    __shared__ AttnSmem sm;
    const int tid = threadIdx.x;
    const int tx  = tid & 63;
    const int ty  = tid >> 6;
    const int q0  = blockIdx.x * 64;
    const int h   = blockIdx.y;
    const int b   = blockIdx.z;
    const int w   = b & (NWIN - 1);

    for (int i = tid; i < TBL; i += 256)
        sm.btab[i] = btab_g[i * HEADS + h];

    {
        const float* qbase = qh + ((size_t)(b * N1V + q0)) * DIM + h * HD;
#pragma unroll
        for (int i = 0; i < 2; i++) {
            int li = tid + i * 256;
            int r  = li >> 3;
            int cq = (li & 7) << 2;
            float4 v = *(const float4*)(qbase + (size_t)r * DIM + cq);
            sm.Qs[r][cq] = v.x; sm.Qs[r][cq + 1] = v.y;
            sm.Qs[r][cq + 2] = v.z; sm.Qs[r][cq + 3] = v.w;
        }
        const float* kbase = kvh + ((size_t)b * N2V) * (2 * DIM) + h * HD;
#pragma unroll
        for (int i = 0; i < 8; i++) {
            int li = tid + i * 256;
            int r  = li >> 3;
            int cq = (li & 7) << 2;
            float4 v = *(const float4*)(kbase + (size_t)r * (2 * DIM) + cq);
            sm.u.K[r][cq] = v.x; sm.u.K[r][cq + 1] = v.y;
            sm.u.K[r][cq + 2] = v.z; sm.u.K[r][cq + 3] = v.w;
        }
    }
    __syncthreads();

    float qreg[32];
#pragma unroll
    for (int c = 0; c < 32; c++) qreg[c] = sm.Qs[tx][c];

    float s[64];
#pragma unroll
    for (int j = 0; j < 64; j++) {
        const float* krow = sm.u.K[ty * 64 + j];
        float acc = 0.f;
#pragma unroll
        for (int c = 0; c < 32; c++) acc = fmaf(qreg[c], krow[c], acc);
        s[j] = acc;
    }
    __syncthreads();

    for (int ch = 0; ch < 4; ch++) {
#pragma unroll
        for (int i = 0; i < 4; i++) {
            int li = tid + i * 256;
            int r  = li >> 4;
            int cq = (li & 15) << 2;
            float4 mv = *(const float4*)(mask + ((size_t)(w * N1V + q0 + r)) * N2V + ch * 64 + cq);
            sm.u.mb.Ms[r][cq] = mv.x; sm.u.mb.Ms[r][cq + 1] = mv.y;
            sm.u.mb.Ms[r][cq + 2] = mv.z; sm.u.mb.Ms[r][cq + 3] = mv.w;
            int4 rv = *(const int4*)(rel + (size_t)(q0 + r) * N2V + ch * 64 + cq);
            sm.u.mb.Ri[r][cq]     = (unsigned short)rv.x;
            sm.u.mb.Ri[r][cq + 1] = (unsigned short)rv.y;
            sm.u.mb.Ri[r][cq + 2] = (unsigned short)rv.z;
            sm.u.mb.Ri[r][cq + 3] = (unsigned short)rv.w;
        }
        __syncthreads();
        if (ty == ch) {
#pragma unroll
            for (int j = 0; j < 64; j++)
                s[j] += sm.u.mb.Ms[tx][j] + sm.btab[sm.u.mb.Ri[tx][j]];
        }
        __syncthreads();
    }

    float m = -1e30f;
#pragma unroll
    for (int j = 0; j < 64; j++) m = fmaxf(m, s[j]);
    sm.red[tx][ty] = m;
    __syncthreads();
    m = fmaxf(fmaxf(sm.red[tx][0], sm.red[tx][1]),
              fmaxf(sm.red[tx][2], sm.red[tx][3]));
    __syncthreads();
    float lsum = 0.f;
#pragma unroll
    for (int j = 0; j < 64; j++) {
        float e = __expf(s[j] - m);
        s[j] = e;
        lsum += e;
    }
    sm.red[tx][ty] = lsum;
    __syncthreads();
    float l = sm.red[tx][0] + sm.red[tx][1] + sm.red[tx][2] + sm.red[tx][3];
    if (ty == 0) sm.linv[tx] = 1.0f / l;

    {
        const float* vbase = kvh + ((size_t)b * N2V) * (2 * DIM) + DIM + h * HD;
#pragma unroll
        for (int i = 0; i < 8; i++) {
            int li = tid + i * 256;
            int r  = li >> 3;
            int cq = (li & 7) << 2;
            float4 v = *(const float4*)(vbase + (size_t)r * (2 * DIM) + cq);
            sm.u.K[r][cq] = v.x; sm.u.K[r][cq + 1] = v.y;
            sm.u.K[r][cq + 2] = v.z; sm.u.K[r][cq + 3] = v.w;
        }
    }
    __syncthreads();

    float o[32];
#pragma unroll
    for (int d = 0; d < 32; d++) o[d] = 0.f;
#pragma unroll
    for (int j = 0; j < 64; j++) {
        float p = s[j];
        const float* vrow = sm.u.K[ty * 64 + j];
#pragma unroll
        for (int d = 0; d < 32; d++) o[d] = fmaf(p, vrow[d], o[d]);
    }

    for (int st = 0; st < 4; st++) {
        if (ty == st) {
            if (st == 0) {
#pragma unroll
                for (int d = 0; d < 32; d++) sm.Qs[tx][d] = o[d];
            } else {
#pragma unroll
                for (int d = 0; d < 32; d++) sm.Qs[tx][d] += o[d];
            }
        }
        __syncthreads();
    }

    // write x as bf16 hi/lo pairs (input for the output projection)
#pragma unroll
    for (int i = 0; i < 4; i++) {
        int lin = tid + i * 256;             // 0..1023 bf16x2 slots (64 q x 16 pairs)
        int qq  = lin >> 4;
        int dp  = lin & 15;
        float linvq = sm.linv[qq];
        float va = sm.Qs[qq][2 * dp]     * linvq;
        float vb = sm.Qs[qq][2 * dp + 1] * linvq;
        __nv_bfloat16 ha = __float2bfloat16_rn(va);
        __nv_bfloat16 hb = __float2bfloat16_rn(vb);
        __nv_bfloat16 la = __float2bfloat16_rn(va - __bfloat162float(ha));
        __nv_bfloat16 lb = __float2bfloat16_rn(vb - __bfloat162float(hb));
        size_t e2 = ((((size_t)(b * N1V + q0 + qq)) * DIM + h * HD) >> 1) + dp;
        __nv_bfloat162 H; H.x = ha; H.y = hb;
        __nv_bfloat162 L; L.x = la; L.y = lb;
        ((__nv_bfloat162*)xhi)[e2] = H;
        ((__nv_bfloat162*)xlo)[e2] = L;
    }
}

// ---------------- launch ----------------
extern "C" void kernel_launch(void* const* d_in, const int* in_sizes, int n_in,
                              void* d_out, int out_size)
{
    const float* q    = (const float*)d_in[0];
    const float* kv   = (const float*)d_in[1];
    const float* mask = (const float*)d_in[2];
    const float* Wq   = (const float*)d_in[3];
    const float* bq   = (const float*)d_in[4];
    const float* Wkv  = (const float*)d_in[5];
    const float* bkv  = (const float*)d_in[6];
    const float* btab = (const float*)d_in[7];
    const float* Wp   = (const float*)d_in[8];
    const float* bp   = (const float*)d_in[9];
    const int*   rel  = (const int*)d_in[10];
    float* out = (float*)d_out;

    static float* qh = nullptr; static float* kvh = nullptr;
    static __nv_bfloat16 *qhi, *qlo, *kvhi, *kvlo, *xhi, *xlo;
    static __nv_bfloat16 *wqhi, *wqlo, *wkvhi, *wkvlo, *wphi, *wplo;
    if (!qh) {
        cudaGetSymbolAddress((void**)&qh,   d_qh);
        cudaGetSymbolAddress((void**)&kvh,  d_kvh);
        cudaGetSymbolAddress((void**)&qhi,  d_qhi);
        cudaGetSymbolAddress((void**)&qlo,  d_qlo);
        cudaGetSymbolAddress((void**)&kvhi, d_kvhi);
        cudaGetSymbolAddress((void**)&kvlo, d_kvlo);
        cudaGetSymbolAddress((void**)&xhi,  d_xhi);
        cudaGetSymbolAddress((void**)&xlo,  d_xlo);
        cudaGetSymbolAddress((void**)&wqhi,  d_wqhi);
        cudaGetSymbolAddress((void**)&wqlo,  d_wqlo);
        cudaGetSymbolAddress((void**)&wkvhi, d_wkvhi);
        cudaGetSymbolAddress((void**)&wkvlo, d_wkvlo);
        cudaGetSymbolAddress((void**)&wphi,  d_wphi);
        cudaGetSymbolAddress((void**)&wplo,  d_wplo);
    }

    const float scale = 0.17677669529663687f;   // 1/sqrt(32)

    // input / weight splits into bf16 hi+lo
    {
        int n2 = MTOT * DIM / 2;
        split_kernel<<<(n2 + 255) / 256, 256>>>(q,  (__nv_bfloat162*)qhi,  (__nv_bfloat162*)qlo,  n2);
        split_kernel<<<(n2 + 255) / 256, 256>>>(kv, (__nv_bfloat162*)kvhi, (__nv_bfloat162*)kvlo, n2);
        int w1 = DIM * DIM / 2, w2 = DIM * DIM;
        split_kernel<<<(w1 + 255) / 256, 256>>>(Wq,  (__nv_bfloat162*)wqhi,  (__nv_bfloat162*)wqlo,  w1);
        split_kernel<<<(w2 + 255) / 256, 256>>>(Wkv, (__nv_bfloat162*)wkvhi, (__nv_bfloat162*)wkvlo, w2);
        split_kernel<<<(w1 + 255) / 256, 256>>>(Wp,  (__nv_bfloat162*)wphi,  (__nv_bfloat162*)wplo,  w1);
    }

    // 1) qh = scale * (q @ Wq^T + bq)
    mma_gemm<<<dim3(DIM / 128, MTOT / 128), 256>>>(qhi, qlo, wqhi, wqlo, bq, qh, DIM, scale);
    // 2) kvh = kv @ Wkv^T + bkv
    mma_gemm<<<dim3(2 * DIM / 128, MTOT / 128), 256>>>(kvhi, kvlo, wkvhi, wkvlo, bkv, kvh, 2 * DIM, 1.f);
    // 3) attention -> xhi/xlo bf16
    attn_kernel<<<dim3(4, HEADS, BTOT), 256>>>(qh, kvh, mask, btab, rel, xhi, xlo);
    // 4) out = x @ Wp^T + bp
    mma_gemm<<<dim3(DIM / 128, MTOT / 128), 256>>>(xhi, xlo, wphi, wplo, bp, out, DIM, 1.f);
}

// round 6
// speedup vs baseline: 1.1317x; 1.1317x over previous
#include <cuda_runtime.h>
#include <cuda_bf16.h>
#include <cstdint>
#include <math.h>

#define DIM    256
#define HEADS  8
#define HD     32
#define N1V    256
#define N2V    256
#define BTOT   256
#define NWIN   128
#define TBL    1575
#define MTOT   (BTOT * N1V)

typedef unsigned long long ull;

// ---------------- scratch (device globals; no allocation) ----------------
__device__ float d_qh [MTOT * DIM];              // scaled Q proj
__device__ float d_kvh[MTOT * 2 * DIM];          // K|V proj
__device__ float d_x  [MTOT * DIM];              // attention output

// ---------------- packed f32x2 helpers (sm_100+ base PTX) ----------------
__device__ __forceinline__ ull pack2(float x, float y) {
    ull r; asm("mov.b64 %0, {%1, %2};" : "=l"(r) : "f"(x), "f"(y)); return r;
}
__device__ __forceinline__ void unpack2(ull v, float& x, float& y) {
    asm("mov.b64 {%0, %1}, %2;" : "=f"(x), "=f"(y) : "l"(v));
}
__device__ __forceinline__ void ffma2(ull& d, ull a, ull b) {
    asm("fma.rn.f32x2 %0, %1, %2, %0;" : "+l"(d) : "l"(a), "l"(b));
}

// ---------------- FFMA2 NT SGEMM: C = alpha * (A @ B^T + bias) -------------
// A: [M,K] row-major, B: [N,K] row-major, bias[N].
// block tile 128x128, k-tile 16, 256 threads, 8x8 per thread (4 f32x2 pairs).
__global__ void __launch_bounds__(256) gemm_nt(
    const float* __restrict__ A, const float* __restrict__ B,
    const float* __restrict__ bias, float* __restrict__ C,
    int M, int N, int K, float alpha)
{
    __shared__ float As[16][132];
    __shared__ float Bs[16][132];
    const int m0  = blockIdx.y * 128;
    const int n0  = blockIdx.x * 128;
    const int tid = threadIdx.x;
    const int tr  = tid >> 4;     // 0..15
    const int tc  = tid & 15;     // 0..15

    ull acc2[8][4];
#pragma unroll
    for (int i = 0; i < 8; i++)
#pragma unroll
        for (int j = 0; j < 4; j++) acc2[i][j] = 0ull;

    for (int k0 = 0; k0 < K; k0 += 16) {
#pragma unroll
        for (int i = 0; i < 2; i++) {
            int li = tid + i * 256;          // 0..511 float4 slots
            int r  = li >> 2;                // 0..127
            int cq = (li & 3) << 2;          // 0,4,8,12
            float4 va = *(const float4*)(A + (size_t)(m0 + r) * K + k0 + cq);
            As[cq + 0][r] = va.x; As[cq + 1][r] = va.y;
            As[cq + 2][r] = va.z; As[cq + 3][r] = va.w;
            float4 vb = *(const float4*)(B + (size_t)(n0 + r) * K + k0 + cq);
            Bs[cq + 0][r] = vb.x; Bs[cq + 1][r] = vb.y;
            Bs[cq + 2][r] = vb.z; Bs[cq + 3][r] = vb.w;
        }
        __syncthreads();
#pragma unroll
        for (int kk = 0; kk < 16; kk++) {
            float4 a0 = *(const float4*)&As[kk][tr * 8];
            float4 a1 = *(const float4*)&As[kk][tr * 8 + 4];
            ull b2[4];
#pragma unroll
            for (int j = 0; j < 4; j++)
                b2[j] = *(const ull*)&Bs[kk][tc * 8 + 2 * j];
            ull ad[8];
            ad[0] = pack2(a0.x, a0.x); ad[1] = pack2(a0.y, a0.y);
            ad[2] = pack2(a0.z, a0.z); ad[3] = pack2(a0.w, a0.w);
            ad[4] = pack2(a1.x, a1.x); ad[5] = pack2(a1.y, a1.y);
            ad[6] = pack2(a1.z, a1.z); ad[7] = pack2(a1.w, a1.w);
#pragma unroll
            for (int i = 0; i < 8; i++)
#pragma unroll
                for (int j = 0; j < 4; j++)
                    ffma2(acc2[i][j], ad[i], b2[j]);
        }
        __syncthreads();
    }

#pragma unroll
    for (int i = 0; i < 8; i++) {
        int r = m0 + tr * 8 + i;
#pragma unroll
        for (int j = 0; j < 4; j++) {
            int c = n0 + tc * 8 + 2 * j;
            float x, y;
            unpack2(acc2[i][j], x, y);
            float2 v;
            v.x = alpha * (x + bias[c]);
            v.y = alpha * (y + bias[c + 1]);
            *(float2*)(C + (size_t)r * N + c) = v;
        }
    }
}

// ---------------- attention kernel (fp32, f32x2 inner loops) ---------------
// grid: (4 q-tiles of 64, HEADS, BTOT), 256 threads
// thread (tx = tid&63 -> query in tile, ty = tid>>6 -> 64-key chunk)
struct __align__(16) AttnSmem {
    union U {
        float K[256][32];                             // K tile, then V tile
        struct { float Ms[64][65]; unsigned short Ri[64][66]; } mb;
    } u;                                              // 32768 B
    float Qs[64][34];                                 // stride 34 -> 8B aligned rows
    float btab[TBL];
    float red[64][4];
    float linv[64];
};

__global__ void __launch_bounds__(256) attn_kernel(
    const float* __restrict__ qh, const float* __restrict__ kvh,
    const float* __restrict__ mask, const float* __restrict__ btab_g,
    const int* __restrict__ rel, float* __restrict__ xout)
{
    __shared__ AttnSmem sm;
    const int tid = threadIdx.x;
    const int tx  = tid & 63;
    const int ty  = tid >> 6;
    const int q0  = blockIdx.x * 64;
    const int h   = blockIdx.y;
    const int b   = blockIdx.z;
    const int w   = b & (NWIN - 1);

    for (int i = tid; i < TBL; i += 256)
        sm.btab[i] = btab_g[i * HEADS + h];

    {
        const float* qbase = qh + ((size_t)(b * N1V + q0)) * DIM + h * HD;
#pragma unroll
        for (int i = 0; i < 2; i++) {
            int li = tid + i * 256;
            int r  = li >> 3;
            int cq = (li & 7) << 2;
            float4 v = *(const float4*)(qbase + (size_t)r * DIM + cq);
            sm.Qs[r][cq] = v.x; sm.Qs[r][cq + 1] = v.y;
            sm.Qs[r][cq + 2] = v.z; sm.Qs[r][cq + 3] = v.w;
        }
        const float* kbase = kvh + ((size_t)b * N2V) * (2 * DIM) + h * HD;
#pragma unroll
        for (int i = 0; i < 8; i++) {
            int li = tid + i * 256;
            int r  = li >> 3;
            int cq = (li & 7) << 2;
            float4 v = *(const float4*)(kbase + (size_t)r * (2 * DIM) + cq);
            sm.u.K[r][cq] = v.x; sm.u.K[r][cq + 1] = v.y;
            sm.u.K[r][cq + 2] = v.z; sm.u.K[r][cq + 3] = v.w;
        }
    }
    __syncthreads();

    // Q row as 16 packed channel-pairs
    ull qp[16];
#pragma unroll
    for (int c = 0; c < 16; c++) qp[c] = *(const ull*)&sm.Qs[tx][2 * c];

    float s[64];
#pragma unroll
    for (int j = 0; j < 64; j++) {
        const float* krow = sm.u.K[ty * 64 + j];
        ull acc = 0ull;
#pragma unroll
        for (int c = 0; c < 16; c++)
            ffma2(acc, qp[c], *(const ull*)&krow[2 * c]);
        float x, y;
        unpack2(acc, x, y);
        s[j] = x + y;
    }
    __syncthreads();

    // add mask + relative-position bias, staged through smem (coalesced)
    for (int ch = 0; ch < 4; ch++) {
#pragma unroll
        for (int i = 0; i < 4; i++) {
            int li = tid + i * 256;
            int r  = li >> 4;
            int cq = (li & 15) << 2;
            float4 mv = *(const float4*)(mask + ((size_t)(w * N1V + q0 + r)) * N2V + ch * 64 + cq);
            sm.u.mb.Ms[r][cq] = mv.x; sm.u.mb.Ms[r][cq + 1] = mv.y;
            sm.u.mb.Ms[r][cq + 2] = mv.z; sm.u.mb.Ms[r][cq + 3] = mv.w;
            int4 rv = *(const int4*)(rel + (size_t)(q0 + r) * N2V + ch * 64 + cq);
            sm.u.mb.Ri[r][cq]     = (unsigned short)rv.x;
            sm.u.mb.Ri[r][cq + 1] = (unsigned short)rv.y;
            sm.u.mb.Ri[r][cq + 2] = (unsigned short)rv.z;
            sm.u.mb.Ri[r][cq + 3] = (unsigned short)rv.w;
        }
        __syncthreads();
        if (ty == ch) {
#pragma unroll
            for (int j = 0; j < 64; j++)
                s[j] += sm.u.mb.Ms[tx][j] + sm.btab[sm.u.mb.Ri[tx][j]];
        }
        __syncthreads();
    }

    // softmax over 256 keys (4 chunks of 64 across ty)
    float m = -1e30f;
#pragma unroll
    for (int j = 0; j < 64; j++) m = fmaxf(m, s[j]);
    sm.red[tx][ty] = m;
    __syncthreads();
    m = fmaxf(fmaxf(sm.red[tx][0], sm.red[tx][1]),
              fmaxf(sm.red[tx][2], sm.red[tx][3]));
    __syncthreads();
    float lsum = 0.f;
#pragma unroll
    for (int j = 0; j < 64; j++) {
        float e = __expf(s[j] - m);
        s[j] = e;
        lsum += e;
    }
    sm.red[tx][ty] = lsum;
    __syncthreads();
    float l = sm.red[tx][0] + sm.red[tx][1] + sm.red[tx][2] + sm.red[tx][3];
    if (ty == 0) sm.linv[tx] = 1.0f / l;

    // load V over the K region
    {
        const float* vbase = kvh + ((size_t)b * N2V) * (2 * DIM) + DIM + h * HD;
#pragma unroll
        for (int i = 0; i < 8; i++) {
            int li = tid + i * 256;
            int r  = li >> 3;
            int cq = (li & 7) << 2;
            float4 v = *(const float4*)(vbase + (size_t)r * (2 * DIM) + cq);
            sm.u.K[r][cq] = v.x; sm.u.K[r][cq + 1] = v.y;
            sm.u.K[r][cq + 2] = v.z; sm.u.K[r][cq + 3] = v.w;
        }
    }
    __syncthreads();

    // O partial in packed pairs: 16 f32x2 accumulators over this thread's 64 keys
    ull o2[16];
#pragma unroll
    for (int d = 0; d < 16; d++) o2[d] = 0ull;
#pragma unroll
    for (int j = 0; j < 64; j++) {
        ull pp = pack2(s[j], s[j]);
        const float* vrow = sm.u.K[ty * 64 + j];
#pragma unroll
        for (int d = 0; d < 16; d++)
            ffma2(o2[d], pp, *(const ull*)&vrow[2 * d]);
    }

    // reduce 4 partial O vectors per query through Qs
    for (int st = 0; st < 4; st++) {
        if (ty == st) {
            if (st == 0) {
#pragma unroll
                for (int d = 0; d < 16; d++)
                    *(ull*)&sm.Qs[tx][2 * d] = o2[d];
            } else {
#pragma unroll
                for (int d = 0; d < 16; d++) {
                    float x, y;
                    unpack2(o2[d], x, y);
                    sm.Qs[tx][2 * d]     += x;
                    sm.Qs[tx][2 * d + 1] += y;
                }
            }
        }
        __syncthreads();
    }

    // write x[b, q, h*32+d] = O / l   (coalesced)
#pragma unroll
    for (int i = 0; i < 8; i++) {
        int lin = tid + i * 256;             // 0..2047
        int q   = lin >> 5;
        int d   = lin & 31;
        xout[((size_t)(b * N1V + q0 + q)) * DIM + h * HD + d] =
            sm.Qs[q][d] * sm.linv[q];
    }
}

// ---------------- launch ----------------
extern "C" void kernel_launch(void* const* d_in, const int* in_sizes, int n_in,
                              void* d_out, int out_size)
{
    const float* q    = (const float*)d_in[0];
    const float* kv   = (const float*)d_in[1];
    const float* mask = (const float*)d_in[2];
    const float* Wq   = (const float*)d_in[3];
    const float* bq   = (const float*)d_in[4];
    const float* Wkv  = (const float*)d_in[5];
    const float* bkv  = (const float*)d_in[6];
    const float* btab = (const float*)d_in[7];
    const float* Wp   = (const float*)d_in[8];
    const float* bp   = (const float*)d_in[9];
    const int*   rel  = (const int*)d_in[10];
    float* out = (float*)d_out;

    static float* qh  = nullptr;
    static float* kvh = nullptr;
    static float* xb  = nullptr;
    if (!qh) {
        cudaGetSymbolAddress((void**)&qh,  d_qh);
        cudaGetSymbolAddress((void**)&kvh, d_kvh);
        cudaGetSymbolAddress((void**)&xb,  d_x);
    }

    const int M = MTOT;                             // 65536
    const float scale = 0.17677669529663687f;       // 1/sqrt(32)

    // 1) qh = scale * (q @ Wq^T + bq)
    gemm_nt<<<dim3(DIM / 128, M / 128), 256>>>(q, Wq, bq, qh, M, DIM, DIM, scale);
    // 2) kvh = kv @ Wkv^T + bkv   (cols 0..255 = K, 256..511 = V)
    gemm_nt<<<dim3((2 * DIM) / 128, M / 128), 256>>>(kv, Wkv, bkv, kvh, M, 2 * DIM, DIM, 1.f);
    // 3) windowed attention with bias + mask + softmax
    attn_kernel<<<dim3(4, HEADS, BTOT), 256>>>(qh, kvh, mask, btab, rel, xb);
    // 4) out = x @ Wp^T + bp
    gemm_nt<<<dim3(DIM / 128, M / 128), 256>>>(xb, Wp, bp, out, M, DIM, DIM, 1.f);
}